// round 2
// baseline (speedup 1.0000x reference)
#include <cuda_runtime.h>
#include <cstddef>

// ---------------------------------------------------------------------------
// SparseGraphLearn:
//   h = inputs @ weight                      [M=100000, K=256] @ [256, N=128]
//   diff = |h[edge0] - h[edge1]|             [E=1600000, 128]
//   edge_weight = relu(diff @ a)             [E]
// Output layout: d_out = [ h (M*128 floats) | edge_weight (E floats) ]
// Inputs (metadata order): inputs f32, edge int32 (2,E)  (JAX x64 disabled ->
// the "int64" randint array is actually int32), weight f32, a f32
// ---------------------------------------------------------------------------

#define TM 64     // rows per block
#define KC 32     // K-chunk
#define KTOT 256
#define NTOT 128

__global__ __launch_bounds__(256) void sgl_gemm_kernel(
    const float* __restrict__ A,   // [M, 256]
    const float* __restrict__ W,   // [256, 128]
    float* __restrict__ H,         // [M, 128]
    int M)
{
    __shared__ float sA[TM][KC];     // 8 KB
    __shared__ float sB[KC][NTOT];   // 16 KB

    const int tx   = threadIdx.x;           // 0..255
    const int colg = (tx & 31) * 4;         // 0,4,...,124 (lane -> 4 cols)
    const int warp = tx >> 5;               // 0..7 -> 8-row group
    const int row0 = blockIdx.x * TM;

    float acc[8][4];
#pragma unroll
    for (int i = 0; i < 8; ++i)
#pragma unroll
        for (int j = 0; j < 4; ++j) acc[i][j] = 0.f;

    for (int k0 = 0; k0 < KTOT; k0 += KC) {
        // Load A tile 64x32 : 512 float4, 2 per thread
#pragma unroll
        for (int i = tx; i < TM * KC / 4; i += 256) {
            int r = i >> 3;             // / (KC/4)
            int c = (i & 7) * 4;
            int gr = row0 + r;
            float4 v = make_float4(0.f, 0.f, 0.f, 0.f);
            if (gr < M)
                v = *(const float4*)(A + (size_t)gr * KTOT + k0 + c);
            *(float4*)&sA[r][c] = v;
        }
        // Load B tile 32x128 : 1024 float4, 4 per thread
#pragma unroll
        for (int i = tx; i < KC * NTOT / 4; i += 256) {
            int r = i >> 5;             // / (NTOT/4)
            int c = (i & 31) * 4;
            *(float4*)&sB[r][c] = *(const float4*)(W + (size_t)(k0 + r) * NTOT + c);
        }
        __syncthreads();

#pragma unroll
        for (int kk = 0; kk < KC; ++kk) {
            float4 b = *(float4*)&sB[kk][colg];       // LDS.128, conflict-free
#pragma unroll
            for (int i = 0; i < 8; ++i) {
                float av = sA[warp * 8 + i][kk];      // broadcast across warp
                acc[i][0] = fmaf(av, b.x, acc[i][0]);
                acc[i][1] = fmaf(av, b.y, acc[i][1]);
                acc[i][2] = fmaf(av, b.z, acc[i][2]);
                acc[i][3] = fmaf(av, b.w, acc[i][3]);
            }
        }
        __syncthreads();
    }

#pragma unroll
    for (int i = 0; i < 8; ++i) {
        int gr = row0 + warp * 8 + i;
        if (gr < M) {
            float4 v = make_float4(acc[i][0], acc[i][1], acc[i][2], acc[i][3]);
            *(float4*)(H + (size_t)gr * NTOT + colg) = v;
        }
    }
}

// One warp per edge. Lane l owns columns [4l, 4l+3]; per endpoint one LDG.128.
// h fits in L2 (51.2 MB), so gathers are L2-resident.
__global__ __launch_bounds__(256) void sgl_edge_kernel(
    const float* __restrict__ H,       // [M, 128]
    const int* __restrict__ edge,      // [2, E] int32
    const float* __restrict__ a,       // [128]
    float* __restrict__ out,           // [E]
    int E)
{
    const int lane = threadIdx.x & 31;
    const int e = (int)(((size_t)blockIdx.x * blockDim.x + threadIdx.x) >> 5);
    if (e >= E) return;

    float4 av = *(const float4*)(a + lane * 4);

    int u = edge[e];
    int v = edge[(size_t)E + e];

    float4 x = *((const float4*)(H + (size_t)u * NTOT) + lane);
    float4 y = *((const float4*)(H + (size_t)v * NTOT) + lane);

    float s = fabsf(x.x - y.x) * av.x
            + fabsf(x.y - y.y) * av.y
            + fabsf(x.z - y.z) * av.z
            + fabsf(x.w - y.w) * av.w;

#pragma unroll
    for (int off = 16; off; off >>= 1)
        s += __shfl_xor_sync(0xffffffffu, s, off);

    if (lane == 0) out[e] = fmaxf(s, 0.f);
}

extern "C" void kernel_launch(void* const* d_in, const int* in_sizes, int n_in,
                              void* d_out, int out_size)
{
    const float* A    = (const float*)d_in[0];      // inputs [M,256]
    const int*   edge = (const int*)d_in[1];        // [2,E] int32
    const float* W    = (const float*)d_in[2];      // [256,128]
    const float* a    = (const float*)d_in[3];      // [128,1]

    const int M = in_sizes[0] / KTOT;
    const int E = in_sizes[1] / 2;

    float* H  = (float*)d_out;                     // [M,128]
    float* ew = (float*)d_out + (size_t)M * NTOT;  // [E]

    int gemm_blocks = (M + TM - 1) / TM;
    sgl_gemm_kernel<<<gemm_blocks, 256>>>(A, W, H, M);

    int edge_blocks = (E + 7) / 8;   // 8 warps per block, warp per edge
    sgl_edge_kernel<<<edge_blocks, 256>>>(H, edge, a, ew, E);
}

// round 3
// speedup vs baseline: 1.2529x; 1.2529x over previous
#include <cuda_runtime.h>
#include <cstddef>

// ---------------------------------------------------------------------------
// SparseGraphLearn:
//   h = inputs @ weight                      [M=100000, K=256] @ [256, N=128]
//   edge_weight = relu(|h[e0]-h[e1]| @ a)    [E=1600000]
// d_out = [ h (M*128 f32) | edge_weight (E f32) ]
// Inputs: inputs f32 [M,256], edge int32 [2,E], weight f32 [256,128], a f32 [128]
// ---------------------------------------------------------------------------

#define TM 64
#define KC 32
#define KTOT 256
#define NTOT 128

__device__ __forceinline__ unsigned long long ffma2(
    unsigned long long a, unsigned long long b, unsigned long long c)
{
    unsigned long long d;
    asm("fma.rn.f32x2 %0, %1, %2, %3;" : "=l"(d) : "l"(a), "l"(b), "l"(c));
    return d;
}

__global__ __launch_bounds__(256) void sgl_gemm_kernel(
    const float* __restrict__ A,   // [M, 256]
    const float* __restrict__ W,   // [256, 128]
    float* __restrict__ H,         // [M, 128]
    int M)
{
    // A tile stored as duplicated pairs (a,a) so LDS.64 feeds FFMA2 directly.
    __shared__ float2 sA2[TM][KC];               // 16 KB
    __shared__ __align__(16) float sB[KC][NTOT]; // 16 KB

    const int tx   = threadIdx.x;        // 0..255
    const int colg = (tx & 31) * 4;      // lane -> 4 cols
    const int warp = tx >> 5;            // 8-row group
    const int row0 = blockIdx.x * TM;

    unsigned long long acc[8][2];        // 8 rows x (2 f32x2 = 4 cols)
#pragma unroll
    for (int i = 0; i < 8; ++i) { acc[i][0] = 0ull; acc[i][1] = 0ull; }

    for (int k0 = 0; k0 < KTOT; k0 += KC) {
        // A tile 64x32: 512 float4, 2 per thread, duplicated into sA2
#pragma unroll
        for (int i = tx; i < TM * KC / 4; i += 256) {
            int r = i >> 3;
            int c = (i & 7) * 4;
            int gr = row0 + r;
            float4 v = make_float4(0.f, 0.f, 0.f, 0.f);
            if (gr < M)
                v = *(const float4*)(A + (size_t)gr * KTOT + k0 + c);
            sA2[r][c + 0] = make_float2(v.x, v.x);
            sA2[r][c + 1] = make_float2(v.y, v.y);
            sA2[r][c + 2] = make_float2(v.z, v.z);
            sA2[r][c + 3] = make_float2(v.w, v.w);
        }
        // B tile 32x128: 1024 float4, 4 per thread
#pragma unroll
        for (int i = tx; i < KC * NTOT / 4; i += 256) {
            int r = i >> 5;
            int c = (i & 31) * 4;
            *(float4*)&sB[r][c] = *(const float4*)(W + (size_t)(k0 + r) * NTOT + c);
        }
        __syncthreads();

#pragma unroll
        for (int kk = 0; kk < KC; ++kk) {
            ulonglong2 b = *(const ulonglong2*)&sB[kk][colg];  // LDS.128: 2 f32x2
#pragma unroll
            for (int i = 0; i < 8; ++i) {
                unsigned long long aa =
                    *(const unsigned long long*)&sA2[warp * 8 + i][kk]; // broadcast LDS.64
                acc[i][0] = ffma2(aa, b.x, acc[i][0]);
                acc[i][1] = ffma2(aa, b.y, acc[i][1]);
            }
        }
        __syncthreads();
    }

#pragma unroll
    for (int i = 0; i < 8; ++i) {
        int gr = row0 + warp * 8 + i;
        if (gr < M) {
            union { unsigned long long u; float2 f; } c0, c1;
            c0.u = acc[i][0]; c1.u = acc[i][1];
            float4 v = make_float4(c0.f.x, c0.f.y, c1.f.x, c1.f.y);
            *(float4*)(H + (size_t)gr * NTOT + colg) = v;
        }
    }
}

// 8 lanes per edge, 4 edges per warp. Lane l of group g owns cols
// {32j + 4l .. 32j+4l+3 : j=0..3} of edge (quad*4+g). Per segment j the 8
// lanes cover one 128B line -> fully coalesced. 3 shfl.xor per 4 edges.
__global__ __launch_bounds__(256) void sgl_edge_kernel(
    const float* __restrict__ H,       // [M, 128]
    const int* __restrict__ edge,      // [2, E] int32
    const float* __restrict__ a,       // [128]
    float* __restrict__ out,           // [E]
    int E)
{
    const int lane = threadIdx.x & 31;
    const int g = lane >> 3;           // edge slot in warp
    const int l = lane & 7;            // lane in group

    // attention vector segments, loaded once per warp
    float4 a0 = *(const float4*)(a +       4 * l);
    float4 a1 = *(const float4*)(a +  32 + 4 * l);
    float4 a2 = *(const float4*)(a +  64 + 4 * l);
    float4 a3 = *(const float4*)(a +  96 + 4 * l);

    const int warp_id = blockIdx.x * (blockDim.x >> 5) + (threadIdx.x >> 5);
    const int nwarps  = gridDim.x * (blockDim.x >> 5);
    const int nquads  = (E + 3) >> 2;

    for (int quad = warp_id; quad < nquads; quad += nwarps) {
        int e = quad * 4 + g;
        bool valid = e < E;
        int ec = valid ? e : 0;

        int u = edge[ec];
        int v = edge[(size_t)E + ec];

        const float4* xp = (const float4*)(H + (size_t)u * NTOT) + l;
        const float4* yp = (const float4*)(H + (size_t)v * NTOT) + l;

        float4 x0 = xp[0], x1 = xp[8], x2 = xp[16], x3 = xp[24];
        float4 y0 = yp[0], y1 = yp[8], y2 = yp[16], y3 = yp[24];

        float s;
        s  = fabsf(x0.x - y0.x) * a0.x;
        s += fabsf(x0.y - y0.y) * a0.y;
        s += fabsf(x0.z - y0.z) * a0.z;
        s += fabsf(x0.w - y0.w) * a0.w;
        s += fabsf(x1.x - y1.x) * a1.x;
        s += fabsf(x1.y - y1.y) * a1.y;
        s += fabsf(x1.z - y1.z) * a1.z;
        s += fabsf(x1.w - y1.w) * a1.w;
        s += fabsf(x2.x - y2.x) * a2.x;
        s += fabsf(x2.y - y2.y) * a2.y;
        s += fabsf(x2.z - y2.z) * a2.z;
        s += fabsf(x2.w - y2.w) * a2.w;
        s += fabsf(x3.x - y3.x) * a3.x;
        s += fabsf(x3.y - y3.y) * a3.y;
        s += fabsf(x3.z - y3.z) * a3.z;
        s += fabsf(x3.w - y3.w) * a3.w;

        s += __shfl_xor_sync(0xffffffffu, s, 1);
        s += __shfl_xor_sync(0xffffffffu, s, 2);
        s += __shfl_xor_sync(0xffffffffu, s, 4);

        if (l == 0 && valid) out[e] = fmaxf(s, 0.f);
    }
}

extern "C" void kernel_launch(void* const* d_in, const int* in_sizes, int n_in,
                              void* d_out, int out_size)
{
    const float* A    = (const float*)d_in[0];
    const int*   edge = (const int*)d_in[1];
    const float* W    = (const float*)d_in[2];
    const float* a    = (const float*)d_in[3];

    const int M = in_sizes[0] / KTOT;
    const int E = in_sizes[1] / 2;

    float* H  = (float*)d_out;
    float* ew = (float*)d_out + (size_t)M * NTOT;

    int gemm_blocks = (M + TM - 1) / TM;
    sgl_gemm_kernel<<<gemm_blocks, 256>>>(A, W, H, M);

    // 8 warps/block, 4 edges/warp, grid-stride over edge quads
    int edge_blocks = 2048;
    sgl_edge_kernel<<<edge_blocks, 256>>>(H, edge, a, ew, E);
}

// round 5
// speedup vs baseline: 1.7756x; 1.4172x over previous
#include <cuda_runtime.h>
#include <cuda_bf16.h>
#include <cstdint>
#include <cstddef>

// ---------------------------------------------------------------------------
// SparseGraphLearn:
//   h = inputs @ weight          [M=100000,256] @ [256,128]  fp32
//   edge_weight = relu(|h[e0]-h[e1]| @ a)   [E]
// d_out = [ h | edge_weight ]
//
// GEMM via mma.sync.m16n8k16 bf16 with 2-term split (3 cross products):
//   x = hi + mid, hi = bf16(x), mid = bf16(x - hi)
//   A*W ~= Ahi*Whi + Ahi*Wmid + Amid*Whi      (fp32 accumulate)
// ---------------------------------------------------------------------------

#define KTOT 256
#define NTOT 128
#define MTILE 128
#define KCH 64
#define LDS_W 36          // smem row stride in 32-bit words (72 bf16 = 144 B)

#define SA_HI  0
#define SA_MID 18432
#define SB_HI  36864
#define SB_MID 55296
#define S_TOTAL 73728

// Pre-split weight, n-major [n][k] bf16 (written by prep_w, read by gemm)
__device__ __nv_bfloat16 g_whi[NTOT * KTOT];
__device__ __nv_bfloat16 g_wmid[NTOT * KTOT];

__device__ __forceinline__ uint32_t pack_bf16x2(float lo, float hi) {
    __nv_bfloat16 l = __float2bfloat16(lo);
    __nv_bfloat16 h = __float2bfloat16(hi);
    return ((uint32_t)__bfloat16_as_ushort(h) << 16) | __bfloat16_as_ushort(l);
}

__device__ __forceinline__ void mma_bf16(float* d, const uint32_t* a, const uint32_t* b) {
    asm volatile(
        "mma.sync.aligned.m16n8k16.row.col.f32.bf16.bf16.f32 "
        "{%0,%1,%2,%3}, {%4,%5,%6,%7}, {%8,%9}, {%0,%1,%2,%3};"
        : "+f"(d[0]), "+f"(d[1]), "+f"(d[2]), "+f"(d[3])
        : "r"(a[0]), "r"(a[1]), "r"(a[2]), "r"(a[3]), "r"(b[0]), "r"(b[1]));
}

// Split W [256,128] row-major -> g_whi/g_wmid [128 n][256 k]
__global__ __launch_bounds__(256) void prep_w(const float* __restrict__ W) {
    int idx = blockIdx.x * 256 + threadIdx.x;   // 32768
    int k = idx >> 7;
    int n = idx & 127;
    float x = W[idx];
    __nv_bfloat16 h = __float2bfloat16(x);
    __nv_bfloat16 m = __float2bfloat16(x - __bfloat162float(h));
    g_whi [n * KTOT + k] = h;
    g_wmid[n * KTOT + k] = m;
}

__global__ __launch_bounds__(512) void sgl_gemm_mma(
    const float* __restrict__ A,   // [M, 256]
    float* __restrict__ H,         // [M, 128]
    int M)
{
    extern __shared__ char smem[];
    uint32_t* sAhi = (uint32_t*)(smem + SA_HI);
    uint32_t* sAmi = (uint32_t*)(smem + SA_MID);
    uint32_t* sBhi = (uint32_t*)(smem + SB_HI);
    uint32_t* sBmi = (uint32_t*)(smem + SB_MID);

    const int tid  = threadIdx.x;
    const int wid  = tid >> 5;
    const int lane = tid & 31;
    const int g    = lane >> 2;       // 0..7
    const int t    = lane & 3;        // 0..3
    const int m0w  = (wid >> 2) * 32; // warp m origin (0,32,64,96)
    const int n0w  = (wid & 3) * 32;  // warp n origin
    const int row0 = blockIdx.x * MTILE;

    float acc[2][4][4];
#pragma unroll
    for (int mt = 0; mt < 2; ++mt)
#pragma unroll
        for (int nt = 0; nt < 4; ++nt)
#pragma unroll
            for (int j = 0; j < 4; ++j) acc[mt][nt][j] = 0.f;

    // A-load mapping: thread -> row r = tid>>2, 64 contiguous bytes (4 float4)
    const int ar = tid >> 2;
    const int at = tid & 3;

    for (int ch = 0; ch < 4; ++ch) {
        const int k0 = ch * KCH;

        // ---- A chunk [128 x 64] -> split bf16 hi/mid into smem ----
        {
            const float4* src = (const float4*)(A + (size_t)(row0 + ar) * KTOT + k0) + at * 4;
            bool ok = (row0 + ar) < M;
#pragma unroll
            for (int j = 0; j < 4; ++j) {
                float4 v = ok ? src[j] : make_float4(0.f, 0.f, 0.f, 0.f);
                float hx = __bfloat162float(__float2bfloat16(v.x));
                float hy = __bfloat162float(__float2bfloat16(v.y));
                float hz = __bfloat162float(__float2bfloat16(v.z));
                float hw = __bfloat162float(__float2bfloat16(v.w));
                int p2 = at * 4 + j;                 // float4 index 0..15
                int w0 = ar * LDS_W + p2 * 2;        // word offset
                uint2 hiw = make_uint2(pack_bf16x2(v.x, v.y), pack_bf16x2(v.z, v.w));
                uint2 miw = make_uint2(pack_bf16x2(v.x - hx, v.y - hy),
                                       pack_bf16x2(v.z - hz, v.w - hw));
                *(uint2*)(sAhi + w0) = hiw;
                *(uint2*)(sAmi + w0) = miw;
            }
        }

        // ---- B chunk: copy pre-split [128 n][64 k] rows from global ----
        {
#pragma unroll
            for (int s = 0; s < 4; ++s) {
                int idx = tid + s * 512;             // 0..2047
                int r = idx >> 4;                    // n row
                int q = idx & 15;                    // uint2 within row
                *(uint2*)(sBhi + r * LDS_W + q * 2) =
                    *((const uint2*)(g_whi + (size_t)r * KTOT + k0) + q);
                *(uint2*)(sBmi + r * LDS_W + q * 2) =
                    *((const uint2*)(g_wmid + (size_t)r * KTOT + k0) + q);
            }
        }
        __syncthreads();

        // ---- 4 k-steps of 16 ----
#pragma unroll
        for (int ks = 0; ks < 4; ++ks) {
            const int kb = ks * 8;    // word base within row

            uint32_t afr[2][2][4];    // [split][mtile][reg]
#pragma unroll
            for (int mt = 0; mt < 2; ++mt) {
                int m = m0w + mt * 16 + g;
                const uint32_t* p0 = sAhi + m * LDS_W + kb + t;
                afr[0][mt][0] = p0[0];
                afr[0][mt][2] = p0[4];
                afr[0][mt][1] = p0[8 * LDS_W];
                afr[0][mt][3] = p0[8 * LDS_W + 4];
                const uint32_t* p1 = sAmi + m * LDS_W + kb + t;
                afr[1][mt][0] = p1[0];
                afr[1][mt][2] = p1[4];
                afr[1][mt][1] = p1[8 * LDS_W];
                afr[1][mt][3] = p1[8 * LDS_W + 4];
            }

            uint32_t bfr[2][4][2];    // [split][ntile][reg]
#pragma unroll
            for (int nt = 0; nt < 4; ++nt) {
                int n = n0w + nt * 8 + g;
                const uint32_t* p0 = sBhi + n * LDS_W + kb + t;
                bfr[0][nt][0] = p0[0];
                bfr[0][nt][1] = p0[4];
                const uint32_t* p1 = sBmi + n * LDS_W + kb + t;
                bfr[1][nt][0] = p1[0];
                bfr[1][nt][1] = p1[4];
            }

#pragma unroll
            for (int mt = 0; mt < 2; ++mt)
#pragma unroll
                for (int nt = 0; nt < 4; ++nt) {
                    mma_bf16(acc[mt][nt], afr[0][mt], bfr[0][nt]);  // hi*hi
                    mma_bf16(acc[mt][nt], afr[0][mt], bfr[1][nt]);  // hi*mid
                    mma_bf16(acc[mt][nt], afr[1][mt], bfr[0][nt]);  // mid*hi
                }
        }
        __syncthreads();
    }

    // ---- Epilogue ----
#pragma unroll
    for (int mt = 0; mt < 2; ++mt)
#pragma unroll
        for (int nt = 0; nt < 4; ++nt) {
            int row = row0 + m0w + mt * 16 + g;
            int col = n0w + nt * 8 + t * 2;
            if (row < M)
                *(float2*)(H + (size_t)row * NTOT + col) =
                    make_float2(acc[mt][nt][0], acc[mt][nt][1]);
            if (row + 8 < M)
                *(float2*)(H + (size_t)(row + 8) * NTOT + col) =
                    make_float2(acc[mt][nt][2], acc[mt][nt][3]);
        }
}

// ---------------------------------------------------------------------------
// Edge kernel (unchanged): 8 lanes/edge, 4 edges/warp, L2-resident h.
// ---------------------------------------------------------------------------
__global__ __launch_bounds__(256) void sgl_edge_kernel(
    const float* __restrict__ H,
    const int* __restrict__ edge,
    const float* __restrict__ a,
    float* __restrict__ out,
    int E)
{
    const int lane = threadIdx.x & 31;
    const int g = lane >> 3;
    const int l = lane & 7;

    float4 a0 = *(const float4*)(a +       4 * l);
    float4 a1 = *(const float4*)(a +  32 + 4 * l);
    float4 a2 = *(const float4*)(a +  64 + 4 * l);
    float4 a3 = *(const float4*)(a +  96 + 4 * l);

    const int warp_id = blockIdx.x * (blockDim.x >> 5) + (threadIdx.x >> 5);
    const int nwarps  = gridDim.x * (blockDim.x >> 5);
    const int nquads  = (E + 3) >> 2;

    for (int quad = warp_id; quad < nquads; quad += nwarps) {
        int e = quad * 4 + g;
        bool valid = e < E;
        int ec = valid ? e : 0;

        int u = edge[ec];
        int v = edge[(size_t)E + ec];

        const float4* xp = (const float4*)(H + (size_t)u * NTOT) + l;
        const float4* yp = (const float4*)(H + (size_t)v * NTOT) + l;

        float4 x0 = xp[0], x1 = xp[8], x2 = xp[16], x3 = xp[24];
        float4 y0 = yp[0], y1 = yp[8], y2 = yp[16], y3 = yp[24];

        float s;
        s  = fabsf(x0.x - y0.x) * a0.x;
        s += fabsf(x0.y - y0.y) * a0.y;
        s += fabsf(x0.z - y0.z) * a0.z;
        s += fabsf(x0.w - y0.w) * a0.w;
        s += fabsf(x1.x - y1.x) * a1.x;
        s += fabsf(x1.y - y1.y) * a1.y;
        s += fabsf(x1.z - y1.z) * a1.z;
        s += fabsf(x1.w - y1.w) * a1.w;
        s += fabsf(x2.x - y2.x) * a2.x;
        s += fabsf(x2.y - y2.y) * a2.y;
        s += fabsf(x2.z - y2.z) * a2.z;
        s += fabsf(x2.w - y2.w) * a2.w;
        s += fabsf(x3.x - y3.x) * a3.x;
        s += fabsf(x3.y - y3.y) * a3.y;
        s += fabsf(x3.z - y3.z) * a3.z;
        s += fabsf(x3.w - y3.w) * a3.w;

        s += __shfl_xor_sync(0xffffffffu, s, 1);
        s += __shfl_xor_sync(0xffffffffu, s, 2);
        s += __shfl_xor_sync(0xffffffffu, s, 4);

        if (l == 0 && valid) out[e] = fmaxf(s, 0.f);
    }
}

extern "C" void kernel_launch(void* const* d_in, const int* in_sizes, int n_in,
                              void* d_out, int out_size)
{
    const float* A    = (const float*)d_in[0];
    const int*   edge = (const int*)d_in[1];
    const float* W    = (const float*)d_in[2];
    const float* a    = (const float*)d_in[3];

    const int M = in_sizes[0] / KTOT;
    const int E = in_sizes[1] / 2;

    float* H  = (float*)d_out;
    float* ew = (float*)d_out + (size_t)M * NTOT;

    cudaFuncSetAttribute(sgl_gemm_mma,
                         cudaFuncAttributeMaxDynamicSharedMemorySize, S_TOTAL);

    prep_w<<<128, 256>>>(W);

    int gemm_blocks = (M + MTILE - 1) / MTILE;
    sgl_gemm_mma<<<gemm_blocks, 512, S_TOTAL>>>(A, H, M);

    int edge_blocks = 2048;
    sgl_edge_kernel<<<edge_blocks, 256>>>(H, edge, a, ew, E);
}

// round 6
// speedup vs baseline: 1.8732x; 1.0549x over previous
#include <cuda_runtime.h>
#include <cuda_bf16.h>
#include <cuda_fp16.h>
#include <cstdint>
#include <cstddef>

// ---------------------------------------------------------------------------
// SparseGraphLearn:
//   h = inputs @ weight          [M=100000,256] @ [256,128]  fp32
//   edge_weight = relu(|h[e0]-h[e1]| @ a)   [E]
// d_out = [ h | edge_weight ]
//
// GEMM: mma.sync.m16n8k16 bf16, 2-term split (3 cross products), ldmatrix
//       fragment loads. Epilogue also writes an fp16 shadow of h.
// Edge: gathers from the fp16 shadow (half the L2 traffic).
// ---------------------------------------------------------------------------

#define KTOT 256
#define NTOT 128
#define MTILE 128
#define KCH 64
#define LDS_W 36          // smem row stride in words (144 B)
#define NMAX 100000

#define SA_HI  0
#define SA_MID 18432
#define SB_HI  36864
#define SB_MID 55296
#define S_TOTAL 73728

__device__ __nv_bfloat16 g_whi[NTOT * KTOT];   // [n][k]
__device__ __nv_bfloat16 g_wmid[NTOT * KTOT];
__device__ __half        g_h16[(size_t)NMAX * NTOT];  // fp16 shadow of h

__device__ __forceinline__ uint32_t pack_bf16x2(float lo, float hi) {
    __nv_bfloat16 l = __float2bfloat16(lo);
    __nv_bfloat16 h = __float2bfloat16(hi);
    return ((uint32_t)__bfloat16_as_ushort(h) << 16) | __bfloat16_as_ushort(l);
}

__device__ __forceinline__ void mma_bf16(float* d, const uint32_t* a, const uint32_t* b) {
    asm volatile(
        "mma.sync.aligned.m16n8k16.row.col.f32.bf16.bf16.f32 "
        "{%0,%1,%2,%3}, {%4,%5,%6,%7}, {%8,%9}, {%0,%1,%2,%3};"
        : "+f"(d[0]), "+f"(d[1]), "+f"(d[2]), "+f"(d[3])
        : "r"(a[0]), "r"(a[1]), "r"(a[2]), "r"(a[3]), "r"(b[0]), "r"(b[1]));
}

__device__ __forceinline__ void ldsm4(uint32_t* r, uint32_t addr) {
    asm volatile("ldmatrix.sync.aligned.m8n8.x4.shared.b16 {%0,%1,%2,%3}, [%4];"
        : "=r"(r[0]), "=r"(r[1]), "=r"(r[2]), "=r"(r[3]) : "r"(addr));
}

__global__ __launch_bounds__(256) void prep_w(const float* __restrict__ W) {
    int idx = blockIdx.x * 256 + threadIdx.x;   // 32768
    int k = idx >> 7;
    int n = idx & 127;
    float x = W[idx];
    __nv_bfloat16 h = __float2bfloat16(x);
    __nv_bfloat16 m = __float2bfloat16(x - __bfloat162float(h));
    g_whi [n * KTOT + k] = h;
    g_wmid[n * KTOT + k] = m;
}

__global__ __launch_bounds__(512) void sgl_gemm_mma(
    const float* __restrict__ A,   // [M, 256]
    float* __restrict__ H,         // [M, 128]
    int M)
{
    extern __shared__ char smem[];
    uint32_t* sAhi = (uint32_t*)(smem + SA_HI);
    uint32_t* sAmi = (uint32_t*)(smem + SA_MID);
    uint32_t* sBhi = (uint32_t*)(smem + SB_HI);
    uint32_t* sBmi = (uint32_t*)(smem + SB_MID);
    const uint32_t sbase = (uint32_t)__cvta_generic_to_shared(smem);

    const int tid  = threadIdx.x;
    const int wid  = tid >> 5;
    const int lane = tid & 31;
    const int g    = lane >> 2;
    const int t    = lane & 3;
    const int m0w  = (wid >> 2) * 32;
    const int n0w  = (wid & 3) * 32;
    const int row0 = blockIdx.x * MTILE;

    // ldmatrix lane->address mapping (word offsets, kb added per k-step)
    const int aRow  = (lane & 7) + ((lane >> 3) & 1) * 8;
    const int aKw   = (lane >> 4) * 4;
    const int baseA0 = (m0w + aRow) * LDS_W + aKw;
    const int baseA1 = (m0w + 16 + aRow) * LDS_W + aKw;
    const int bRow  = lane & 7;
    const int bNt   = lane >> 4;             // nt within pair
    const int bKw   = ((lane >> 3) & 1) * 4;
    const int baseB0 = (n0w + (0 + bNt) * 8 + bRow) * LDS_W + bKw;  // nt pair 0 (nt0,nt1)
    const int baseB1 = (n0w + (2 + bNt) * 8 + bRow) * LDS_W + bKw;  // nt pair 1 (nt2,nt3)

    float acc[2][4][4];
#pragma unroll
    for (int mt = 0; mt < 2; ++mt)
#pragma unroll
        for (int nt = 0; nt < 4; ++nt)
#pragma unroll
            for (int j = 0; j < 4; ++j) acc[mt][nt][j] = 0.f;

    const int ar = tid >> 2;
    const int at = tid & 3;

    for (int ch = 0; ch < 4; ++ch) {
        const int k0 = ch * KCH;

        // ---- A chunk [128 x 64] -> split bf16 hi/mid into smem ----
        {
            const float4* src = (const float4*)(A + (size_t)(row0 + ar) * KTOT + k0) + at * 4;
            bool ok = (row0 + ar) < M;
#pragma unroll
            for (int j = 0; j < 4; ++j) {
                float4 v = ok ? src[j] : make_float4(0.f, 0.f, 0.f, 0.f);
                float hx = __bfloat162float(__float2bfloat16(v.x));
                float hy = __bfloat162float(__float2bfloat16(v.y));
                float hz = __bfloat162float(__float2bfloat16(v.z));
                float hw = __bfloat162float(__float2bfloat16(v.w));
                int p2 = at * 4 + j;
                int w0 = ar * LDS_W + p2 * 2;
                *(uint2*)(sAhi + w0) = make_uint2(pack_bf16x2(v.x, v.y), pack_bf16x2(v.z, v.w));
                *(uint2*)(sAmi + w0) = make_uint2(pack_bf16x2(v.x - hx, v.y - hy),
                                                  pack_bf16x2(v.z - hz, v.w - hw));
            }
        }

        // ---- B chunk: copy pre-split [128 n][64 k] from global ----
        {
#pragma unroll
            for (int s = 0; s < 4; ++s) {
                int idx = tid + s * 512;
                int r = idx >> 4;
                int q = idx & 15;
                *(uint2*)(sBhi + r * LDS_W + q * 2) =
                    *((const uint2*)(g_whi + (size_t)r * KTOT + k0) + q);
                *(uint2*)(sBmi + r * LDS_W + q * 2) =
                    *((const uint2*)(g_wmid + (size_t)r * KTOT + k0) + q);
            }
        }
        __syncthreads();

#pragma unroll
        for (int ks = 0; ks < 4; ++ks) {
            const int kw = ks * 8 * 4;   // byte offset for k-step

            uint32_t afr[2][2][4];
            ldsm4(afr[0][0], sbase + SA_HI  + baseA0 * 4 + kw);
            ldsm4(afr[0][1], sbase + SA_HI  + baseA1 * 4 + kw);
            ldsm4(afr[1][0], sbase + SA_MID + baseA0 * 4 + kw);
            ldsm4(afr[1][1], sbase + SA_MID + baseA1 * 4 + kw);

            uint32_t bfr[2][8];          // [split][nt*2 + reg]
            ldsm4(&bfr[0][0], sbase + SB_HI  + baseB0 * 4 + kw);
            ldsm4(&bfr[0][4], sbase + SB_HI  + baseB1 * 4 + kw);
            ldsm4(&bfr[1][0], sbase + SB_MID + baseB0 * 4 + kw);
            ldsm4(&bfr[1][4], sbase + SB_MID + baseB1 * 4 + kw);

#pragma unroll
            for (int mt = 0; mt < 2; ++mt)
#pragma unroll
                for (int nt = 0; nt < 4; ++nt) {
                    mma_bf16(acc[mt][nt], afr[0][mt], &bfr[0][nt * 2]);  // hi*hi
                    mma_bf16(acc[mt][nt], afr[0][mt], &bfr[1][nt * 2]);  // hi*mid
                    mma_bf16(acc[mt][nt], afr[1][mt], &bfr[0][nt * 2]);  // mid*hi
                }
        }
        __syncthreads();
    }

    // ---- Epilogue: fp32 H + fp16 shadow ----
#pragma unroll
    for (int mt = 0; mt < 2; ++mt)
#pragma unroll
        for (int nt = 0; nt < 4; ++nt) {
            int row = row0 + m0w + mt * 16 + g;
            int col = n0w + nt * 8 + t * 2;
            if (row < M) {
                *(float2*)(H + (size_t)row * NTOT + col) =
                    make_float2(acc[mt][nt][0], acc[mt][nt][1]);
                *(__half2*)(g_h16 + (size_t)row * NTOT + col) =
                    __floats2half2_rn(acc[mt][nt][0], acc[mt][nt][1]);
            }
            if (row + 8 < M) {
                *(float2*)(H + (size_t)(row + 8) * NTOT + col) =
                    make_float2(acc[mt][nt][2], acc[mt][nt][3]);
                *(__half2*)(g_h16 + (size_t)(row + 8) * NTOT + col) =
                    __floats2half2_rn(acc[mt][nt][2], acc[mt][nt][3]);
            }
        }
}

// ---------------------------------------------------------------------------
// Edge kernel on the fp16 shadow: 8 lanes/edge, 4 edges/warp.
// Lane l owns cols [8l,8l+7] and [64+8l,64+8l+7] (2x 16B per endpoint).
// ---------------------------------------------------------------------------
__device__ __forceinline__ float dot8_absdiff(uint4 x, uint4 y,
                                              float4 a0, float4 a1) {
    float2 fx0 = __half22float2(*(__half2*)&x.x), fy0 = __half22float2(*(__half2*)&y.x);
    float2 fx1 = __half22float2(*(__half2*)&x.y), fy1 = __half22float2(*(__half2*)&y.y);
    float2 fx2 = __half22float2(*(__half2*)&x.z), fy2 = __half22float2(*(__half2*)&y.z);
    float2 fx3 = __half22float2(*(__half2*)&x.w), fy3 = __half22float2(*(__half2*)&y.w);
    float s;
    s  = fabsf(fx0.x - fy0.x) * a0.x;
    s += fabsf(fx0.y - fy0.y) * a0.y;
    s += fabsf(fx1.x - fy1.x) * a0.z;
    s += fabsf(fx1.y - fy1.y) * a0.w;
    s += fabsf(fx2.x - fy2.x) * a1.x;
    s += fabsf(fx2.y - fy2.y) * a1.y;
    s += fabsf(fx3.x - fy3.x) * a1.z;
    s += fabsf(fx3.y - fy3.y) * a1.w;
    return s;
}

__global__ __launch_bounds__(256) void sgl_edge_kernel(
    const int* __restrict__ edge,
    const float* __restrict__ a,
    float* __restrict__ out,
    int E)
{
    const int lane = threadIdx.x & 31;
    const int g = lane >> 3;
    const int l = lane & 7;

    float4 aA0 = *(const float4*)(a +      8 * l);
    float4 aA1 = *(const float4*)(a +      8 * l + 4);
    float4 aB0 = *(const float4*)(a + 64 + 8 * l);
    float4 aB1 = *(const float4*)(a + 64 + 8 * l + 4);

    const int warp_id = blockIdx.x * (blockDim.x >> 5) + (threadIdx.x >> 5);
    const int nwarps  = gridDim.x * (blockDim.x >> 5);
    const int nquads  = (E + 3) >> 2;

    for (int quad = warp_id; quad < nquads; quad += nwarps) {
        int e = quad * 4 + g;
        bool valid = e < E;
        int ec = valid ? e : 0;

        int u = edge[ec];
        int v = edge[(size_t)E + ec];

        const uint4* xp = (const uint4*)(g_h16 + (size_t)u * NTOT) + l;
        const uint4* yp = (const uint4*)(g_h16 + (size_t)v * NTOT) + l;

        uint4 x0 = xp[0], x1 = xp[8];
        uint4 y0 = yp[0], y1 = yp[8];

        float s = dot8_absdiff(x0, y0, aA0, aA1)
                + dot8_absdiff(x1, y1, aB0, aB1);

        s += __shfl_xor_sync(0xffffffffu, s, 1);
        s += __shfl_xor_sync(0xffffffffu, s, 2);
        s += __shfl_xor_sync(0xffffffffu, s, 4);

        if (l == 0 && valid) out[e] = fmaxf(s, 0.f);
    }
}

extern "C" void kernel_launch(void* const* d_in, const int* in_sizes, int n_in,
                              void* d_out, int out_size)
{
    const float* A    = (const float*)d_in[0];
    const int*   edge = (const int*)d_in[1];
    const float* W    = (const float*)d_in[2];
    const float* a    = (const float*)d_in[3];

    const int M = in_sizes[0] / KTOT;
    const int E = in_sizes[1] / 2;

    float* H  = (float*)d_out;
    float* ew = (float*)d_out + (size_t)M * NTOT;

    cudaFuncSetAttribute(sgl_gemm_mma,
                         cudaFuncAttributeMaxDynamicSharedMemorySize, S_TOTAL);

    prep_w<<<128, 256>>>(W);

    int gemm_blocks = (M + MTILE - 1) / MTILE;
    sgl_gemm_mma<<<gemm_blocks, 512, S_TOTAL>>>(A, H, M);

    int edge_blocks = 2048;
    sgl_edge_kernel<<<edge_blocks, 256>>>(edge, a, ew, E);
}

// round 8
// speedup vs baseline: 2.0168x; 1.0767x over previous
#include <cuda_runtime.h>
#include <cuda_bf16.h>
#include <cuda_fp16.h>
#include <cstdint>
#include <cstddef>

// ---------------------------------------------------------------------------
// SparseGraphLearn:
//   h = inputs @ weight          [M=100000,256] @ [256,128]  fp32
//   edge_weight = relu(|h[e0]-h[e1]| @ a)   [E]
// d_out = [ h | edge_weight ]
//
// GEMM: mma.sync m16n8k16 bf16, truncation 2-term split (3 cross products):
//   hi = trunc16(x)  (pure byte ops),  mid = bf16_rn(x - hi)  (exact sub)
//   A*W ~= Ahi*Whi + Ahi*Wmid + Amid*Whi   fp32 acc
// Edge: gathers from fp16 shadow of h.
// ---------------------------------------------------------------------------

#define KTOT 256
#define NTOT 128
#define MTILE 128
#define KCH 64
#define LDS_W 36
#define NMAX 100000

#define SA_HI  0
#define SA_MID 18432
#define SB_HI  36864
#define SB_MID 55296
#define S_TOTAL 73728

__device__ __nv_bfloat16 g_whi[NTOT * KTOT];   // [n][k]
__device__ __nv_bfloat16 g_wmid[NTOT * KTOT];
__device__ __half        g_h16[(size_t)NMAX * NTOT];

__device__ __forceinline__ void mma_bf16(float* d, const uint32_t* a, const uint32_t* b) {
    asm volatile(
        "mma.sync.aligned.m16n8k16.row.col.f32.bf16.bf16.f32 "
        "{%0,%1,%2,%3}, {%4,%5,%6,%7}, {%8,%9}, {%0,%1,%2,%3};"
        : "+f"(d[0]), "+f"(d[1]), "+f"(d[2]), "+f"(d[3])
        : "r"(a[0]), "r"(a[1]), "r"(a[2]), "r"(a[3]), "r"(b[0]), "r"(b[1]));
}

__device__ __forceinline__ void ldsm4(uint32_t* r, uint32_t addr) {
    asm volatile("ldmatrix.sync.aligned.m8n8.x4.shared.b16 {%0,%1,%2,%3}, [%4];"
        : "=r"(r[0]), "=r"(r[1]), "=r"(r[2]), "=r"(r[3]) : "r"(addr));
}

// Split two fp32 -> (hi bf16x2 via truncation, mid bf16x2 rn). 6 ops total.
__device__ __forceinline__ void split2(float x, float y,
                                       uint32_t& hi, uint32_t& mid) {
    uint32_t ux = __float_as_uint(x), uy = __float_as_uint(y);
    hi = __byte_perm(ux, uy, 0x7632);                  // {lo=hi16(x), hi=hi16(y)}
    float fx = x - __uint_as_float(ux & 0xFFFF0000u);  // exact remainder
    float fy = y - __uint_as_float(uy & 0xFFFF0000u);
    __nv_bfloat162 m = __floats2bfloat162_rn(fx, fy);  // one cvt.bf16x2
    mid = *(uint32_t*)&m;
}

__global__ __launch_bounds__(256) void prep_w(const float* __restrict__ W) {
    int idx = blockIdx.x * 256 + threadIdx.x;   // 32768
    int k = idx >> 7;
    int n = idx & 127;
    float x = W[idx];
    uint32_t ux = __float_as_uint(x);
    uint32_t hib = ux & 0xFFFF0000u;
    float mid = x - __uint_as_float(hib);
    g_whi [n * KTOT + k] = __ushort_as_bfloat16((unsigned short)(ux >> 16));
    g_wmid[n * KTOT + k] = __float2bfloat16(mid);
}

__global__ __launch_bounds__(512) void sgl_gemm_mma(
    const float* __restrict__ A,   // [M, 256]
    float* __restrict__ H,         // [M, 128]
    int M)
{
    extern __shared__ char smem[];
    uint32_t* sAhi = (uint32_t*)(smem + SA_HI);
    uint32_t* sAmi = (uint32_t*)(smem + SA_MID);
    uint32_t* sBhi = (uint32_t*)(smem + SB_HI);
    uint32_t* sBmi = (uint32_t*)(smem + SB_MID);
    const uint32_t sbase = (uint32_t)__cvta_generic_to_shared(smem);

    const int tid  = threadIdx.x;
    const int wid  = tid >> 5;
    const int lane = tid & 31;
    const int g    = lane >> 2;
    const int t    = lane & 3;
    const int m0w  = (wid >> 2) * 32;
    const int n0w  = (wid & 3) * 32;
    const int row0 = blockIdx.x * MTILE;

    const int aRow  = (lane & 7) + ((lane >> 3) & 1) * 8;
    const int aKw   = (lane >> 4) * 4;
    const int baseA0 = (m0w + aRow) * LDS_W + aKw;
    const int baseA1 = (m0w + 16 + aRow) * LDS_W + aKw;
    const int bRow  = lane & 7;
    const int bNt   = lane >> 4;
    const int bKw   = ((lane >> 3) & 1) * 4;
    const int baseB0 = (n0w + (0 + bNt) * 8 + bRow) * LDS_W + bKw;
    const int baseB1 = (n0w + (2 + bNt) * 8 + bRow) * LDS_W + bKw;

    float acc[2][4][4];
#pragma unroll
    for (int mt = 0; mt < 2; ++mt)
#pragma unroll
        for (int nt = 0; nt < 4; ++nt)
#pragma unroll
            for (int j = 0; j < 4; ++j) acc[mt][nt][j] = 0.f;

    const int ar = tid >> 2;       // A row within tile
    const int at = tid & 3;        // quarter-row
    const bool arok = (row0 + ar) < M;
    const float4* arow = (const float4*)(A + (size_t)(row0 + ar) * KTOT);

    float4 v[4];
    // prologue: chunk 0
#pragma unroll
    for (int j = 0; j < 4; ++j)
        v[j] = arok ? arow[at * 4 + j] : make_float4(0.f, 0.f, 0.f, 0.f);

    for (int ch = 0; ch < 4; ++ch) {
        const int k0 = ch * KCH;

        // ---- convert + store A chunk (truncation split, cheap) ----
#pragma unroll
        for (int j = 0; j < 4; ++j) {
            uint32_t h0, m0, h1, m1;
            split2(v[j].x, v[j].y, h0, m0);
            split2(v[j].z, v[j].w, h1, m1);
            int w0 = ar * LDS_W + (at * 4 + j) * 2;
            *(uint2*)(sAhi + w0) = make_uint2(h0, h1);
            *(uint2*)(sAmi + w0) = make_uint2(m0, m1);
        }

        // ---- B chunk copy from pre-split global ----
#pragma unroll
        for (int s = 0; s < 4; ++s) {
            int idx = tid + s * 512;
            int r = idx >> 4;
            int q = idx & 15;
            *(uint2*)(sBhi + r * LDS_W + q * 2) =
                *((const uint2*)(g_whi + (size_t)r * KTOT + k0) + q);
            *(uint2*)(sBmi + r * LDS_W + q * 2) =
                *((const uint2*)(g_wmid + (size_t)r * KTOT + k0) + q);
        }
        __syncthreads();

        // ---- prefetch next A chunk (hidden behind MMA phase) ----
        if (ch < 3) {
            const float4* src = arow + (ch + 1) * (KCH / 4) + at * 4;
#pragma unroll
            for (int j = 0; j < 4; ++j)
                v[j] = arok ? src[j] : make_float4(0.f, 0.f, 0.f, 0.f);
        }

        // ---- MMA over 4 k-steps ----
#pragma unroll
        for (int ks = 0; ks < 4; ++ks) {
            const int kw = ks * 8 * 4;

            uint32_t afr[2][2][4];
            ldsm4(afr[0][0], sbase + SA_HI  + baseA0 * 4 + kw);
            ldsm4(afr[0][1], sbase + SA_HI  + baseA1 * 4 + kw);
            ldsm4(afr[1][0], sbase + SA_MID + baseA0 * 4 + kw);
            ldsm4(afr[1][1], sbase + SA_MID + baseA1 * 4 + kw);

            uint32_t bfr[2][8];
            ldsm4(&bfr[0][0], sbase + SB_HI  + baseB0 * 4 + kw);
            ldsm4(&bfr[0][4], sbase + SB_HI  + baseB1 * 4 + kw);
            ldsm4(&bfr[1][0], sbase + SB_MID + baseB0 * 4 + kw);
            ldsm4(&bfr[1][4], sbase + SB_MID + baseB1 * 4 + kw);

#pragma unroll
            for (int mt = 0; mt < 2; ++mt)
#pragma unroll
                for (int nt = 0; nt < 4; ++nt) {
                    mma_bf16(acc[mt][nt], afr[0][mt], &bfr[0][nt * 2]);  // hi*hi
                    mma_bf16(acc[mt][nt], afr[0][mt], &bfr[1][nt * 2]);  // hi*mid
                    mma_bf16(acc[mt][nt], afr[1][mt], &bfr[0][nt * 2]);  // mid*hi
                }
        }
        __syncthreads();
    }

    // ---- Epilogue: fp32 H + fp16 shadow ----
#pragma unroll
    for (int mt = 0; mt < 2; ++mt)
#pragma unroll
        for (int nt = 0; nt < 4; ++nt) {
            int row = row0 + m0w + mt * 16 + g;
            int col = n0w + nt * 8 + t * 2;
            if (row < M) {
                *(float2*)(H + (size_t)row * NTOT + col) =
                    make_float2(acc[mt][nt][0], acc[mt][nt][1]);
                *(__half2*)(g_h16 + (size_t)row * NTOT + col) =
                    __floats2half2_rn(acc[mt][nt][0], acc[mt][nt][1]);
            }
            if (row + 8 < M) {
                *(float2*)(H + (size_t)(row + 8) * NTOT + col) =
                    make_float2(acc[mt][nt][2], acc[mt][nt][3]);
                *(__half2*)(g_h16 + (size_t)(row + 8) * NTOT + col) =
                    __floats2half2_rn(acc[mt][nt][2], acc[mt][nt][3]);
            }
        }
}

// ---------------------------------------------------------------------------
// Edge kernel on fp16 shadow: 8 lanes/edge, 4 edges/warp.
// ---------------------------------------------------------------------------
__device__ __forceinline__ float dot8_absdiff(uint4 x, uint4 y,
                                              float4 a0, float4 a1) {
    float2 fx0 = __half22float2(*(__half2*)&x.x), fy0 = __half22float2(*(__half2*)&y.x);
    float2 fx1 = __half22float2(*(__half2*)&x.y), fy1 = __half22float2(*(__half2*)&y.y);
    float2 fx2 = __half22float2(*(__half2*)&x.z), fy2 = __half22float2(*(__half2*)&y.z);
    float2 fx3 = __half22float2(*(__half2*)&x.w), fy3 = __half22float2(*(__half2*)&y.w);
    float s;
    s  = fabsf(fx0.x - fy0.x) * a0.x;
    s += fabsf(fx0.y - fy0.y) * a0.y;
    s += fabsf(fx1.x - fy1.x) * a0.z;
    s += fabsf(fx1.y - fy1.y) * a0.w;
    s += fabsf(fx2.x - fy2.x) * a1.x;
    s += fabsf(fx2.y - fy2.y) * a1.y;
    s += fabsf(fx3.x - fy3.x) * a1.z;
    s += fabsf(fx3.y - fy3.y) * a1.w;
    return s;
}

__global__ __launch_bounds__(256) void sgl_edge_kernel(
    const int* __restrict__ edge,
    const float* __restrict__ a,
    float* __restrict__ out,
    int E)
{
    const int lane = threadIdx.x & 31;
    const int g = lane >> 3;
    const int l = lane & 7;

    float4 aA0 = *(const float4*)(a +      8 * l);
    float4 aA1 = *(const float4*)(a +      8 * l + 4);
    float4 aB0 = *(const float4*)(a + 64 + 8 * l);
    float4 aB1 = *(const float4*)(a + 64 + 8 * l + 4);

    const int warp_id = blockIdx.x * (blockDim.x >> 5) + (threadIdx.x >> 5);
    const int nwarps  = gridDim.x * (blockDim.x >> 5);
    const int nquads  = (E + 3) >> 2;

    for (int quad = warp_id; quad < nquads; quad += nwarps) {
        int e = quad * 4 + g;
        bool valid = e < E;
        int ec = valid ? e : 0;

        int u = edge[ec];
        int v = edge[(size_t)E + ec];

        const uint4* xp = (const uint4*)(g_h16 + (size_t)u * NTOT) + l;
        const uint4* yp = (const uint4*)(g_h16 + (size_t)v * NTOT) + l;

        uint4 x0 = xp[0], x1 = xp[8];
        uint4 y0 = yp[0], y1 = yp[8];

        float s = dot8_absdiff(x0, y0, aA0, aA1)
                + dot8_absdiff(x1, y1, aB0, aB1);

        s += __shfl_xor_sync(0xffffffffu, s, 1);
        s += __shfl_xor_sync(0xffffffffu, s, 2);
        s += __shfl_xor_sync(0xffffffffu, s, 4);

        if (l == 0 && valid) out[e] = fmaxf(s, 0.f);
    }
}

extern "C" void kernel_launch(void* const* d_in, const int* in_sizes, int n_in,
                              void* d_out, int out_size)
{
    const float* A    = (const float*)d_in[0];
    const int*   edge = (const int*)d_in[1];
    const float* W    = (const float*)d_in[2];
    const float* a    = (const float*)d_in[3];

    const int M = in_sizes[0] / KTOT;
    const int E = in_sizes[1] / 2;

    float* H  = (float*)d_out;
    float* ew = (float*)d_out + (size_t)M * NTOT;

    cudaFuncSetAttribute(sgl_gemm_mma,
                         cudaFuncAttributeMaxDynamicSharedMemorySize, S_TOTAL);

    prep_w<<<128, 256>>>(W);

    int gemm_blocks = (M + MTILE - 1) / MTILE;
    sgl_gemm_mma<<<gemm_blocks, 512, S_TOTAL>>>(A, H, M);

    int edge_blocks = 2048;
    sgl_edge_kernel<<<edge_blocks, 256>>>(edge, a, ew, E);
}